// round 12
// baseline (speedup 1.0000x reference)
#include <cuda_runtime.h>
#include <math.h>

#define NF   24
#define FS   8
#define DY   32
#define DX   32
#define SEQL 300
#define TOTAL (NF*FS*DY*DX*SEQL)   // 58,982,400 floats
#define N4    (TOTAL/4)            // 14,745,600 float4
#define ROW4  75

#define B1    1125                 // <=1184 co-resident (148 SM * 8 blk @ <=32 regs)
#define THR   256

#define CHUNK 256                  // float4 per warp-chunk (2 rounds of 4/lane)
#define NCH   (N4 / CHUNK)         // 57600

#define FS_STRIDE (DY*DX*SEQL)     // 307200 floats between fs slices
#define B_POS     (NF*16*10)       // 3840 bbox spatial positions

__device__ float    g_partial[B1];
__device__ unsigned g_count;           // returns to 0 every run (zero-init)
__device__ unsigned g_chunk;           // work-steal counter; reset at barrier
__device__ volatile unsigned g_sense;  // sense-reversing barrier

// Hand-evaluated Python bbox math: left = int(32*l), w = int(32*round(l+0.3,4)) - left
__constant__ int c_left[NF] = {
    1, 2, 2, 3, 4, 5, 5, 6, 7, 7, 8, 9,
    9, 10, 11, 12, 12, 13, 14, 14, 15, 16, 16, 17
};
__constant__ int c_w[NF] = {
    10, 9, 10, 10, 9, 9, 10, 10, 9, 10, 10, 9,
    10, 10, 9, 9, 10, 10, 9, 10, 10, 9, 10, 10
};
__constant__ int c_edge_tok[6] = {2, 3, 9, 10, 11, 108};

__device__ __forceinline__ bool sel_tok(int s) {
    return ((unsigned)(s - 9) < 100u) || ((s & ~1) == 2);
}

// weaken multipliers for float4 slot j = i % 75 (seq 4j..4j+3)
__device__ __forceinline__ float4 mult_for(int j) {
    int s0 = j * 4;
    float4 m;
    m.x = sel_tok(s0    ) ? 0.918f : 1.0f;
    m.y = sel_tok(s0 + 1) ? 0.918f : 1.0f;
    m.z = sel_tok(s0 + 2) ? 0.918f : 1.0f;
    m.w = sel_tok(s0 + 3) ? 0.918f : 1.0f;
    return m;
}

// normalized gaussian weight for (yrow, xoff) given bbox width w (9 or 10)
__device__ __forceinline__ float gauss_w(int yrow, int xoff, int w) {
    const float dx = (float)yrow * (16.0f / 15.0f) - 8.0f;
    float ax = ((8.0f / 15.0f) * (8.0f / 15.0f) - dx * dx) * (9.0f / 512.0f);
    float dy, dymin2, inv2sy2;
    if (w == 10) {
        dy = (float)xoff * (10.0f / 9.0f) - 5.0f;
        dymin2 = (5.0f / 9.0f) * (5.0f / 9.0f);
        inv2sy2 = 9.0f / 200.0f;
    } else {
        dy = (float)xoff * (9.0f / 8.0f) - 4.0f;
        dymin2 = 0.25f;
        inv2sy2 = 1.0f / 18.0f;
    }
    return __expf(ax + (dymin2 - dy * dy) * inv2sy2);
}

// one round: 4 batched LDG.128 at base+lane+{0,32,64,96}, weaken, max, store
__device__ __forceinline__ void round4(
    const float4* __restrict__ in4, float4* __restrict__ out4,
    int base, int lane, float& mx)
{
    float4 v[4];
    int idx[4];
    #pragma unroll
    for (int k = 0; k < 4; k++) idx[k] = base + k * 32 + lane;
    #pragma unroll
    for (int k = 0; k < 4; k++) v[k] = __ldcs(in4 + idx[k]);
    #pragma unroll
    for (int k = 0; k < 4; k++) {
        float4 x = v[k];
        mx = fmaxf(mx, fmaxf(fmaxf(x.x, x.y), fmaxf(x.z, x.w)));
        float4 m = mult_for(idx[k] % ROW4);
        __stcs(out4 + idx[k],
               make_float4(x.x * m.x, x.y * m.y, x.z * m.z, x.w * m.w));
    }
}

__global__ void __launch_bounds__(THR, 8)
fused_kernel(const float4* __restrict__ in4, float4* __restrict__ out4,
             const float* __restrict__ in, float* __restrict__ out) {
    const int tid  = threadIdx.x;
    const int bid  = blockIdx.x;
    const int lane = tid & 31;
    const int wid  = tid >> 5;
    const unsigned cur_sense = g_sense;   // read before anyone flips it

    __shared__ float sm[8];
    __shared__ float s_gmax;

    // ===== phase 1: work-stolen weaken + max (472 MB stream, balanced) ======
    float mx = 0.f;
    unsigned c;
    if (lane == 0) c = atomicAdd(&g_chunk, 1u);
    c = __shfl_sync(0xffffffffu, c, 0);
    while (c < NCH) {
        const int base = (int)c * CHUNK;
        round4(in4, out4, base,       lane, mx);
        round4(in4, out4, base + 128, lane, mx);
        if (lane == 0) c = atomicAdd(&g_chunk, 1u);
        c = __shfl_sync(0xffffffffu, c, 0);
    }

    // block max -> g_partial[bid]
    #pragma unroll
    for (int off = 16; off; off >>= 1)
        mx = fmaxf(mx, __shfl_xor_sync(0xffffffffu, mx, off));
    if (lane == 0) sm[wid] = mx;
    __syncthreads();
    if (tid < 8) {
        mx = sm[tid];
        #pragma unroll
        for (int off = 4; off; off >>= 1)
            mx = fmaxf(mx, __shfl_xor_sync(0xffu, mx, off));
        if (tid == 0) g_partial[bid] = mx;
    }

    // ================= grid-wide barrier (sense-reversing) ===================
    __syncthreads();
    if (tid == 0) {
        __threadfence();                                  // publish g_partial
        unsigned old = atomicAdd(&g_count, 1);
        if (old == B1 - 1) {
            g_count = 0;                                  // reset for next replay
            g_chunk = 0;                                  // reset work counter
            __threadfence();
            g_sense = cur_sense ^ 1u;                     // release
        } else {
            while (g_sense == cur_sense) __nanosleep(64);
            __threadfence();                              // acquire
        }
    }
    __syncthreads();

    // ================= global max from 1125 partials =========================
    float pm = 0.f;
    #pragma unroll
    for (int j = tid; j < B1; j += THR)                   // 5 strided reads
        pm = fmaxf(pm, __ldcg(&g_partial[j]));
    #pragma unroll
    for (int off = 16; off; off >>= 1)
        pm = fmaxf(pm, __shfl_xor_sync(0xffffffffu, pm, off));
    if (lane == 0) sm[wid] = pm;
    __syncthreads();
    if (tid < 8) {
        pm = sm[tid];
        #pragma unroll
        for (int off = 4; off; off >>= 1)
            pm = fmaxf(pm, __shfl_xor_sync(0xffu, pm, off));
        if (tid == 0) s_gmax = pm;
    }
    __syncthreads();
    const float gmax = s_gmax;

    // ===== phase 2: strengthen. warp per (position, fs-half), 7680 warps =====
    const int W = bid * 8 + wid;          // [0, 9000)
    if (W >= B_POS * 2) return;
    const int half = W & 1;
    int pos = W >> 1;
    const int xoff = pos % 10;  pos /= 10;
    const int yrow = pos & 15;
    const int f    = pos >> 4;
    const int w    = c_w[f];
    if (xoff >= w) return;                // warp-uniform

    const float add = 0.125f * gauss_w(yrow, xoff, w) * gmax;
    const long base = (long)((f * FS + half * 4) * DY + 8 + yrow) * DX * SEQL
                    + (long)(c_left[f] + xoff) * SEQL;

    if (lane < 24) {
        const int tok = 12 + 4 * lane;    // 16B-aligned: row*300 ≡ 0 mod 4
        float4 v[4];
        #pragma unroll
        for (int r = 0; r < 4; r++)
            v[r] = __ldcs((const float4*)(in + base + (long)r * FS_STRIDE + tok));
        #pragma unroll
        for (int r = 0; r < 4; r++)
            __stcs((float4*)(out + base + (long)r * FS_STRIDE + tok),
                   make_float4(v[r].x + add, v[r].y + add,
                               v[r].z + add, v[r].w + add));
    } else if (lane < 30) {
        const int tok = c_edge_tok[lane - 24];
        float v[4];
        #pragma unroll
        for (int r = 0; r < 4; r++)
            v[r] = __ldcs(in + base + (long)r * FS_STRIDE + tok);
        #pragma unroll
        for (int r = 0; r < 4; r++)
            __stcs(out + base + (long)r * FS_STRIDE + tok, v[r] + add);
    }
}

extern "C" void kernel_launch(void* const* d_in, const int* in_sizes, int n_in,
                              void* d_out, int out_size) {
    const float* in = (const float*)d_in[0];
    float* out = (float*)d_out;
    fused_kernel<<<B1, THR>>>((const float4*)in, (float4*)out, in, out);
}

// round 13
// speedup vs baseline: 1.2554x; 1.2554x over previous
#include <cuda_runtime.h>
#include <math.h>

#define NF   24
#define FS   8
#define DY   32
#define DX   32
#define SEQL 300
#define TOTAL (NF*FS*DY*DX*SEQL)   // 58,982,400 floats
#define N4    (TOTAL/4)            // 14,745,600 float4
#define ROW4  75

#define B1    1125                 // <=1184 co-resident (148 SM * 8 blk @ <=32 regs)
#define THR   256
#define T1    (B1*THR)             // 288000 = 75*3840 -> t%75 invariant in static part

#define SSLOTS    40               // static slots/thread: 40*288000 = 11,520,000 float4
#define STATIC_N4 (SSLOTS*T1)      // 11,520,000
#define CHUNK     512              // float4 per stolen warp-chunk (16/lane)
#define NCH       ((N4-STATIC_N4)/CHUNK)   // 6300 exactly

#define FS_STRIDE (DY*DX*SEQL)     // 307200 floats between fs slices
#define B_POS     (NF*16*10)       // 3840 bbox spatial positions

__device__ float    g_partial[B1];
__device__ unsigned g_count;           // returns to 0 every run (zero-init)
__device__ unsigned g_chunk;           // steal counter; reset by barrier releaser
__device__ volatile unsigned g_sense;  // sense-reversing barrier

// Hand-evaluated Python bbox math: left = int(32*l), w = int(32*round(l+0.3,4)) - left
__constant__ int c_left[NF] = {
    1, 2, 2, 3, 4, 5, 5, 6, 7, 7, 8, 9,
    9, 10, 11, 12, 12, 13, 14, 14, 15, 16, 16, 17
};
__constant__ int c_w[NF] = {
    10, 9, 10, 10, 9, 9, 10, 10, 9, 10, 10, 9,
    10, 10, 9, 9, 10, 10, 9, 10, 10, 9, 10, 10
};
__constant__ int c_edge_tok[6] = {2, 3, 9, 10, 11, 108};

__device__ __forceinline__ bool sel_tok(int s) {
    return ((unsigned)(s - 9) < 100u) || ((s & ~1) == 2);
}

// weaken multipliers for float4 slot j = i % 75 (seq 4j..4j+3)
__device__ __forceinline__ float4 mult_for(int j) {
    int s0 = j * 4;
    float4 m;
    m.x = sel_tok(s0    ) ? 0.918f : 1.0f;
    m.y = sel_tok(s0 + 1) ? 0.918f : 1.0f;
    m.z = sel_tok(s0 + 2) ? 0.918f : 1.0f;
    m.w = sel_tok(s0 + 3) ? 0.918f : 1.0f;
    return m;
}

// normalized gaussian weight for (yrow, xoff) given bbox width w (9 or 10)
__device__ __forceinline__ float gauss_w(int yrow, int xoff, int w) {
    const float dx = (float)yrow * (16.0f / 15.0f) - 8.0f;
    float ax = ((8.0f / 15.0f) * (8.0f / 15.0f) - dx * dx) * (9.0f / 512.0f);
    float dy, dymin2, inv2sy2;
    if (w == 10) {
        dy = (float)xoff * (10.0f / 9.0f) - 5.0f;
        dymin2 = (5.0f / 9.0f) * (5.0f / 9.0f);
        inv2sy2 = 9.0f / 200.0f;
    } else {
        dy = (float)xoff * (9.0f / 8.0f) - 4.0f;
        dymin2 = 0.25f;
        inv2sy2 = 1.0f / 18.0f;
    }
    return __expf(ax + (dymin2 - dy * dy) * inv2sy2);
}

// one stolen round: 4 batched LDG.128 at base+lane+{0,32,64,96}
__device__ __forceinline__ void round4(
    const float4* __restrict__ in4, float4* __restrict__ out4,
    int base, int lane, float& mx)
{
    float4 v[4];
    int idx[4];
    #pragma unroll
    for (int k = 0; k < 4; k++) idx[k] = base + k * 32 + lane;
    #pragma unroll
    for (int k = 0; k < 4; k++) v[k] = __ldcs(in4 + idx[k]);
    #pragma unroll
    for (int k = 0; k < 4; k++) {
        float4 x = v[k];
        mx = fmaxf(mx, fmaxf(fmaxf(x.x, x.y), fmaxf(x.z, x.w)));
        float4 m = mult_for(idx[k] % ROW4);
        __stcs(out4 + idx[k],
               make_float4(x.x * m.x, x.y * m.y, x.z * m.z, x.w * m.w));
    }
}

__global__ void __launch_bounds__(THR, 8)
fused_kernel(const float4* __restrict__ in4, float4* __restrict__ out4,
             const float* __restrict__ in, float* __restrict__ out) {
    const int tid  = threadIdx.x;
    const int bid  = blockIdx.x;
    const int lane = tid & 31;
    const int wid  = tid >> 5;
    const unsigned cur_sense = g_sense;   // read before anyone flips it

    __shared__ float sm[8];
    __shared__ float s_gmax;

    // ===== phase 1a: STATIC interleaved stream (78% of work, atomic-free) ====
    const int t  = bid * THR + tid;
    const int s0 = (t % ROW4) * 4;        // invariant: T1 = 75*3840
    float4 m;
    m.x = sel_tok(s0    ) ? 0.918f : 1.0f;
    m.y = sel_tok(s0 + 1) ? 0.918f : 1.0f;
    m.z = sel_tok(s0 + 2) ? 0.918f : 1.0f;
    m.w = sel_tok(s0 + 3) ? 0.918f : 1.0f;

    float mx = 0.f;
    #pragma unroll 4
    for (int k = 0; k < SSLOTS; k++) {
        const int i = t + k * T1;
        float4 x = __ldcs(in4 + i);
        mx = fmaxf(mx, fmaxf(fmaxf(x.x, x.y), fmaxf(x.z, x.w)));
        __stcs(out4 + i, make_float4(x.x * m.x, x.y * m.y, x.z * m.z, x.w * m.w));
    }

    // ===== phase 1b: STOLEN tail (22%, ~0.7 chunks/warp balances the finish) =
    unsigned c;
    if (lane == 0) c = atomicAdd(&g_chunk, 1u);
    c = __shfl_sync(0xffffffffu, c, 0);
    while (c < NCH) {
        const int base = STATIC_N4 + (int)c * CHUNK;
        round4(in4, out4, base,       lane, mx);
        round4(in4, out4, base + 128, lane, mx);
        round4(in4, out4, base + 256, lane, mx);
        round4(in4, out4, base + 384, lane, mx);
        if (lane == 0) c = atomicAdd(&g_chunk, 1u);
        c = __shfl_sync(0xffffffffu, c, 0);
    }

    // block max -> g_partial[bid]
    #pragma unroll
    for (int off = 16; off; off >>= 1)
        mx = fmaxf(mx, __shfl_xor_sync(0xffffffffu, mx, off));
    if (lane == 0) sm[wid] = mx;
    __syncthreads();
    if (tid < 8) {
        mx = sm[tid];
        #pragma unroll
        for (int off = 4; off; off >>= 1)
            mx = fmaxf(mx, __shfl_xor_sync(0xffu, mx, off));
        if (tid == 0) g_partial[bid] = mx;
    }

    // ================= grid-wide barrier (sense-reversing) ===================
    __syncthreads();
    if (tid == 0) {
        __threadfence();                                  // publish g_partial
        unsigned old = atomicAdd(&g_count, 1);
        if (old == B1 - 1) {
            g_count = 0;                                  // reset for next replay
            g_chunk = 0;                                  // reset steal counter
            __threadfence();
            g_sense = cur_sense ^ 1u;                     // release
        } else {
            while (g_sense == cur_sense) __nanosleep(64);
            __threadfence();                              // acquire
        }
    }
    __syncthreads();

    // ================= global max from 1125 partials =========================
    float pm = 0.f;
    #pragma unroll
    for (int j = tid; j < B1; j += THR)                   // 5 strided reads
        pm = fmaxf(pm, __ldcg(&g_partial[j]));
    #pragma unroll
    for (int off = 16; off; off >>= 1)
        pm = fmaxf(pm, __shfl_xor_sync(0xffffffffu, pm, off));
    if (lane == 0) sm[wid] = pm;
    __syncthreads();
    if (tid < 8) {
        pm = sm[tid];
        #pragma unroll
        for (int off = 4; off; off >>= 1)
            pm = fmaxf(pm, __shfl_xor_sync(0xffu, pm, off));
        if (tid == 0) s_gmax = pm;
    }
    __syncthreads();
    const float gmax = s_gmax;

    // ===== phase 2: strengthen. warp per (position, fs-half), 7680 warps =====
    const int W = bid * 8 + wid;          // [0, 9000)
    if (W >= B_POS * 2) return;
    const int half = W & 1;
    int pos = W >> 1;
    const int xoff = pos % 10;  pos /= 10;
    const int yrow = pos & 15;
    const int f    = pos >> 4;
    const int w    = c_w[f];
    if (xoff >= w) return;                // warp-uniform

    const float add = 0.125f * gauss_w(yrow, xoff, w) * gmax;
    const long base = (long)((f * FS + half * 4) * DY + 8 + yrow) * DX * SEQL
                    + (long)(c_left[f] + xoff) * SEQL;

    if (lane < 24) {
        const int tok = 12 + 4 * lane;    // 16B-aligned: row*300 ≡ 0 mod 4
        float4 v[4];
        #pragma unroll
        for (int r = 0; r < 4; r++)
            v[r] = __ldcs((const float4*)(in + base + (long)r * FS_STRIDE + tok));
        #pragma unroll
        for (int r = 0; r < 4; r++)
            __stcs((float4*)(out + base + (long)r * FS_STRIDE + tok),
                   make_float4(v[r].x + add, v[r].y + add,
                               v[r].z + add, v[r].w + add));
    } else if (lane < 30) {
        const int tok = c_edge_tok[lane - 24];
        float v[4];
        #pragma unroll
        for (int r = 0; r < 4; r++)
            v[r] = __ldcs(in + base + (long)r * FS_STRIDE + tok);
        #pragma unroll
        for (int r = 0; r < 4; r++)
            __stcs(out + base + (long)r * FS_STRIDE + tok, v[r] + add);
    }
}

extern "C" void kernel_launch(void* const* d_in, const int* in_sizes, int n_in,
                              void* d_out, int out_size) {
    const float* in = (const float*)d_in[0];
    float* out = (float*)d_out;
    fused_kernel<<<B1, THR>>>((const float4*)in, (float4*)out, in, out);
}